// round 4
// baseline (speedup 1.0000x reference)
#include <cuda_runtime.h>
#include <mma.h>
#include <cuda_fp16.h>
#include <cstdint>

#define BB 256
#define TT 2048
#define HH 64

typedef unsigned long long u64;
using namespace nvcuda;

// ---------- scratch ----------
__device__ __half g_out1h[(size_t)BB * TT * 128];  // layer-1 output, fp16 [B,T,128]
__device__ float  g_pre2[(size_t)BB * TT * 256];   // layer-2 input preact (no bias)
__device__ __half g_W2h[256 * 128];                // Wih2 in fp16

// ---------- packed fp32x2 (sm_103a FFMA2) ----------
__device__ __forceinline__ u64 ffma2(u64 a, u64 b, u64 c) {
    u64 d; asm("fma.rn.f32x2 %0, %1, %2, %3;" : "=l"(d) : "l"(a), "l"(b), "l"(c)); return d;
}
__device__ __forceinline__ u64 fadd2(u64 a, u64 b) {
    u64 d; asm("add.rn.f32x2 %0, %1, %2;" : "=l"(d) : "l"(a), "l"(b)); return d;
}
__device__ __forceinline__ float2 uf2(u64 v) {
    float2 r; asm("mov.b64 {%0, %1}, %2;" : "=f"(r.x), "=f"(r.y) : "l"(v)); return r;
}

// ---------- MUFU.TANH activations ----------
__device__ __forceinline__ float tanh_f(float x) {
    float y; asm("tanh.approx.f32 %0, %1;" : "=f"(y) : "f"(x)); return y;
}
__device__ __forceinline__ float sigmoid_f(float x) {
    return fmaf(tanh_f(0.5f * x), 0.5f, 0.5f);
}

// =====================================================================
// Wih2 -> fp16 (runs every launch; deterministic)
// =====================================================================
__global__ void cvt_w2(const float* __restrict__ W) {
    int i = blockIdx.x * blockDim.x + threadIdx.x;
    if (i < 256 * 128) g_W2h[i] = __float2half_rn(W[i]);
}

// =====================================================================
// Layer-1 scan: block = (sample pair, direction); 256 threads, 1 gate each
// for two samples. Epilogue distributed over all 8 warps (16 lanes each).
// =====================================================================
__global__ __launch_bounds__(256, 2)
void l1_scan(const float* __restrict__ x,
             const float* __restrict__ Wih_f, const float* __restrict__ Whh_f, const float* __restrict__ b_f,
             const float* __restrict__ Wih_b, const float* __restrict__ Whh_b, const float* __restrict__ b_b)
{
    const int pair = blockIdx.x & 127;
    const int dir  = blockIdx.x >> 7;
    const int s0   = pair * 2;
    const int g    = threadIdx.x;
    const int lane = g & 31, wrp = g >> 5;

    const float* Wih = dir ? Wih_b : Wih_f;
    const float* Whh = dir ? Whh_b : Whh_f;
    const float* bv  = dir ? b_b   : b_f;

    u64 w[32];
    const u64* wrow = (const u64*)(Whh + g * HH);
#pragma unroll
    for (int k = 0; k < 32; k++) w[k] = wrow[k];

    const float4 wi = *(const float4*)(Wih + g * 4);
    const float bias = bv[g];

    __shared__ float hs[2][64];
    __shared__ float sact[2][256];

    if (g < 128) hs[g >> 6][g & 63] = 0.f;
    float c = 0.f;
    __syncthreads();

    const int step = dir ? -1 : 1;
    const int t0   = dir ? TT - 1 : 0;
    const float4* xp0 = (const float4*)(x + (size_t)s0 * TT * 4) + t0;
    const float4* xp1 = (const float4*)(x + (size_t)(s0 + 1) * TT * 4) + t0;

    // epilogue assignment: warp wrp, lanes 0..15 -> item = wrp*16+lane
    const bool epi = (lane < 16);
    const int item = wrp * 16 + lane;          // 0..127
    const int smp  = item >> 6, j = item & 63;
    __half* optr = g_out1h + (size_t)(s0 + smp) * TT * 128 + (size_t)t0 * 128 + dir * HH + j;

    float4 xa0 = __ldg(xp0), xa1 = __ldg(xp0 + step);
    float4 xb0 = __ldg(xp1), xb1 = __ldg(xp1 + step);

    for (int t = 0; t < TT; t++) {
        float4 xa2, xb2;
        if (t + 2 < TT) { xa2 = __ldg(xp0 + 2 * step); xb2 = __ldg(xp1 + 2 * step); }
        else            { xa2 = make_float4(0.f,0.f,0.f,0.f); xb2 = xa2; }

        const ulonglong2* H0 = (const ulonglong2*)hs[0];
        const ulonglong2* H1 = (const ulonglong2*)hs[1];
        u64 a0=0ull,a1=0ull,a2=0ull,a3=0ull;
        u64 d0=0ull,d1=0ull,d2=0ull,d3=0ull;
#pragma unroll
        for (int k = 0; k < 16; k += 2) {
            ulonglong2 v0 = H0[k],     u0 = H1[k];
            ulonglong2 v1 = H0[k + 1], u1 = H1[k + 1];
            a0 = ffma2(w[2*k + 0], v0.x, a0);
            a1 = ffma2(w[2*k + 1], v0.y, a1);
            d0 = ffma2(w[2*k + 0], u0.x, d0);
            d1 = ffma2(w[2*k + 1], u0.y, d1);
            a2 = ffma2(w[2*k + 2], v1.x, a2);
            a3 = ffma2(w[2*k + 3], v1.y, a3);
            d2 = ffma2(w[2*k + 2], u1.x, d2);
            d3 = ffma2(w[2*k + 3], u1.y, d3);
        }
        float2 ra = uf2(fadd2(fadd2(a0, a1), fadd2(a2, a3)));
        float2 rb = uf2(fadd2(fadd2(d0, d1), fadd2(d2, d3)));
        float pre0 = (ra.x + ra.y) + bias
                   + wi.x * xa0.x + wi.y * xa0.y + wi.z * xa0.z + wi.w * xa0.w;
        float pre1 = (rb.x + rb.y) + bias
                   + wi.x * xb0.x + wi.y * xb0.y + wi.z * xb0.z + wi.w * xb0.w;

        const bool isg = (g >= 128 && g < 192);
        sact[0][g] = isg ? tanh_f(pre0) : sigmoid_f(pre0);
        sact[1][g] = isg ? tanh_f(pre1) : sigmoid_f(pre1);
        __syncthreads();

        if (epi) {
            float iv = sact[smp][j],       fv = sact[smp][64 + j];
            float gv = sact[smp][128 + j], ov = sact[smp][192 + j];
            c = fv * c + iv * gv;
            float h = ov * tanh_f(c);
            hs[smp][j] = h;
            *optr = __float2half_rn(h);
            optr += step * 128;
        }
        __syncthreads();

        xa0 = xa1; xa1 = xa2; xb0 = xb1; xb1 = xb2;
        xp0 += step; xp1 += step;
    }
}

// =====================================================================
// pre2 GEMM (fp16 WMMA m16n16k16): pre2[m,n] = sum_k out1h[m,k]*W2h[n,k]
// =====================================================================
__global__ __launch_bounds__(256, 2)
void pre2_wmma(void)
{
    const int w  = threadIdx.x >> 5;
    const int m0 = blockIdx.x * 64;

    __shared__ __half As[64 * 136];   // 17.4 KB, padded rows (136*2=272B, 16B-mult)

    {
        const uint4* src = (const uint4*)(g_out1h + (size_t)m0 * 128);  // 16 uint4/row
        for (int i = threadIdx.x; i < 64 * 16; i += 256) {
            int rr = i >> 4, cc = i & 15;
            *(uint4*)&As[rr * 136 + cc * 8] = src[i];
        }
    }
    __syncthreads();

#pragma unroll 1
    for (int half_i = 0; half_i < 2; half_i++) {
        const int n0 = (w * 2 + half_i) * 16;

        wmma::fragment<wmma::matrix_b, 16, 16, 16, __half, wmma::col_major> bf[8];
#pragma unroll
        for (int k = 0; k < 8; k++)
            wmma::load_matrix_sync(bf[k], g_W2h + (size_t)n0 * 128 + k * 16, 128);

#pragma unroll 1
        for (int m = 0; m < 4; m++) {
            wmma::fragment<wmma::accumulator, 16, 16, 16, float> acc;
            wmma::fill_fragment(acc, 0.f);
#pragma unroll
            for (int k = 0; k < 8; k++) {
                wmma::fragment<wmma::matrix_a, 16, 16, 16, __half, wmma::row_major> af;
                wmma::load_matrix_sync(af, &As[(m * 16) * 136 + k * 16], 136);
                wmma::mma_sync(acc, af, bf[k], acc);
            }
            wmma::store_matrix_sync(g_pre2 + (size_t)(m0 + m * 16) * 256 + n0, acc, 256,
                                    wmma::mem_row_major);
        }
    }
}

// =====================================================================
// Layer-2 scan: block = 2 samples, 256 threads (weights shared).
// Distributed epilogue; fused FC.
// =====================================================================
__global__ __launch_bounds__(256, 2)
void l2_scan(const float* __restrict__ Whh2, const float* __restrict__ b2,
             const float* __restrict__ Wfc, const float* __restrict__ bfc,
             float* __restrict__ out)
{
    const int s0 = blockIdx.x * 2;
    const int g  = threadIdx.x;
    const int lane = g & 31, wrp = g >> 5;

    u64 w[32];
    const u64* wrow = (const u64*)(Whh2 + g * HH);
#pragma unroll
    for (int k = 0; k < 32; k++) w[k] = wrow[k];
    const float bias = b2[g];

    __shared__ float hs[2][64];
    __shared__ float sact[2][256];
    __shared__ float sred[128];

    if (g < 128) hs[g >> 6][g & 63] = 0.f;
    float c = 0.f;
    __syncthreads();

    const bool epi = (lane < 16);
    const int item = wrp * 16 + lane;
    const int smp  = item >> 6, j = item & 63;

    const float* prow0 = g_pre2 + (size_t)s0 * TT * 256 + g;
    const float* prow1 = prow0 + (size_t)TT * 256;
    float pa0 = __ldg(prow0),       pb0 = __ldg(prow1);
    float pa1 = __ldg(prow0 + 256), pb1 = __ldg(prow1 + 256);
    float pa2 = __ldg(prow0 + 512), pb2 = __ldg(prow1 + 512);

    for (int t = 0; t < TT; t++) {
        float pa3 = 0.f, pb3 = 0.f;
        if (t + 3 < TT) {
            pa3 = __ldg(prow0 + (size_t)(t + 3) * 256);
            pb3 = __ldg(prow1 + (size_t)(t + 3) * 256);
        }

        const ulonglong2* H0 = (const ulonglong2*)hs[0];
        const ulonglong2* H1 = (const ulonglong2*)hs[1];
        u64 a0=0ull,a1=0ull,a2=0ull,a3=0ull;
        u64 d0=0ull,d1=0ull,d2=0ull,d3=0ull;
#pragma unroll
        for (int k = 0; k < 16; k += 2) {
            ulonglong2 v0 = H0[k],     u0 = H1[k];
            ulonglong2 v1 = H0[k + 1], u1 = H1[k + 1];
            a0 = ffma2(w[2*k + 0], v0.x, a0);
            a1 = ffma2(w[2*k + 1], v0.y, a1);
            d0 = ffma2(w[2*k + 0], u0.x, d0);
            d1 = ffma2(w[2*k + 1], u0.y, d1);
            a2 = ffma2(w[2*k + 2], v1.x, a2);
            a3 = ffma2(w[2*k + 3], v1.y, a3);
            d2 = ffma2(w[2*k + 2], u1.x, d2);
            d3 = ffma2(w[2*k + 3], u1.y, d3);
        }
        float2 ra = uf2(fadd2(fadd2(a0, a1), fadd2(a2, a3)));
        float2 rb = uf2(fadd2(fadd2(d0, d1), fadd2(d2, d3)));
        float pre0 = (ra.x + ra.y) + pa0 + bias;
        float pre1 = (rb.x + rb.y) + pb0 + bias;

        const bool isg = (g >= 128 && g < 192);
        sact[0][g] = isg ? tanh_f(pre0) : sigmoid_f(pre0);
        sact[1][g] = isg ? tanh_f(pre1) : sigmoid_f(pre1);
        __syncthreads();

        if (epi) {
            float iv = sact[smp][j],       fv = sact[smp][64 + j];
            float gv = sact[smp][128 + j], ov = sact[smp][192 + j];
            c = fv * c + iv * gv;
            hs[smp][j] = ov * tanh_f(c);
        }
        __syncthreads();

        pa0 = pa1; pa1 = pa2; pa2 = pa3;
        pb0 = pb1; pb1 = pb2; pb2 = pb3;
    }

    if (g < 128) sred[g] = hs[g >> 6][g & 63] * __ldg(Wfc + (g & 63));
    __syncthreads();
    if (g < 2) {
        float acc = __ldg(bfc);
#pragma unroll
        for (int k = 0; k < 64; k++) acc += sred[g * 64 + k];
        out[s0 + g] = acc;
    }
}

// =====================================================================
extern "C" void kernel_launch(void* const* d_in, const int* in_sizes, int n_in,
                              void* d_out, int out_size)
{
    const float* x     = (const float*)d_in[0];
    const float* Wih_f = (const float*)d_in[1];
    const float* Whh_f = (const float*)d_in[2];
    const float* b_f   = (const float*)d_in[3];
    const float* Wih_b = (const float*)d_in[4];
    const float* Whh_b = (const float*)d_in[5];
    const float* b_b   = (const float*)d_in[6];
    const float* Wih2  = (const float*)d_in[7];
    const float* Whh2  = (const float*)d_in[8];
    const float* b2    = (const float*)d_in[9];
    const float* Wfc   = (const float*)d_in[10];
    const float* bfc   = (const float*)d_in[11];
    float* out = (float*)d_out;

    cvt_w2<<<64, 512>>>(Wih2);
    l1_scan<<<256, 256>>>(x, Wih_f, Whh_f, b_f, Wih_b, Whh_b, b_b);
    pre2_wmma<<<(BB * TT) / 64, 256>>>();
    l2_scan<<<BB / 2, 256>>>(Whh2, b2, Wfc, bfc, out);
}